// round 6
// baseline (speedup 1.0000x reference)
#include <cuda_runtime.h>

// APPNP: h_{k+1} = (1-a) * Dinv(A+I)Dinv * h_k + a * x,  K=5, a=0.8
// g = dinv .* h (fp32). m[v] = dinv[v]*(g[v] + sum_{e:col=v} g[row_e]).
// 3-kernel preprocessing:
//   k_hist          counts + within-node ranks (entry invariant: ecount=0,total=0)
//   k_alloc         atomic segment alloc -> colstart/colend, dinv
//   k_scatter_fused rank-based scatter + g0=dinv*x + re-zero ecount/total for next replay
// Propagate: warp/node, 16 edges/iter, prefetched epilogue.

#define NN 100000
#define EE 1600000
#define DD 48
#define DV 12           // float4 chunks per fp32 row
#define ALPHA 0.8f

// ---------------- device scratch (static, no allocation) ----------------
__device__ int    g_ecount[NN];     // zero at every kernel_launch entry (invariant)
__device__ int    g_total;          // zero at entry (invariant)
__device__ float  g_dinv[NN];
__device__ int    g_colstart[NN];
__device__ int    g_colend[NN];
__device__ int    g_rank[EE];
__device__ int    g_csr_row[EE];
__device__ float4 g_bufA[NN * DV];
__device__ float4 g_bufB[NN * DV];

static __device__ __forceinline__ float4 f4add(float4 a, float4 b) {
    return make_float4(a.x + b.x, a.y + b.y, a.z + b.z, a.w + b.w);
}

// ---------------- preprocessing ----------------
// histogram; atomic return value = within-node rank of this edge
__global__ void k_hist(const int* __restrict__ col) {
    int e = blockIdx.x * blockDim.x + threadIdx.x;
    if (e < EE) g_rank[e] = atomicAdd(&g_ecount[col[e]], 1);
}

// claim contiguous segment per node; compute dinv
__global__ void k_alloc() {
    int v = blockIdx.x * blockDim.x + threadIdx.x;
    if (v < NN) {
        int c = g_ecount[v];
        int p = atomicAdd(&g_total, c);
        g_colstart[v] = p;
        g_colend[v]   = p + c;
        g_dinv[v]     = rsqrtf((float)(c + 1));   // +1 self loop
    }
}

// scatter (atomic-free) + scale_x + restore zero-invariant for next replay
__global__ void k_scatter_fused(const int* __restrict__ row, const int* __restrict__ col,
                                const float4* __restrict__ x, float4* __restrict__ g0) {
    int t = blockIdx.x * blockDim.x + threadIdx.x;
    if (t < EE) {
        int p = g_colstart[col[t]] + g_rank[t];
        g_csr_row[p] = row[t];
    }
    if (t < NN * DV) {                 // g0 = dinv .* x
        int v = t / DV;
        float s = g_dinv[v];
        float4 a = x[t];
        g0[t] = make_float4(a.x * s, a.y * s, a.z * s, a.w * s);
    }
    if (t < NN) g_ecount[t] = 0;       // ecount is dead after k_alloc; re-zero
    if (t == 0) g_total = 0;
}

// ---------------- propagation ----------------
// Warp per node. el = lane>>2 (8 edge slots), q = lane&3.
// Epilogue operands (g[v], x[v], dinv[v]) prefetched before the edge loop.
template <bool WRITE_H>
__global__ void __launch_bounds__(256) k_propagate(const float4* __restrict__ gin,
                                                   const float4* __restrict__ x,
                                                   float4* __restrict__ gout) {
    int v    = (blockIdx.x * blockDim.x + threadIdx.x) >> 5;
    int lane = threadIdx.x & 31;
    if (v >= NN) return;

    int el = lane >> 2;
    int q  = lane & 3;

    int s    = g_colstart[v];
    int eend = g_colend[v];

    // prefetch epilogue operands (independent of the edge loop)
    float  di = g_dinv[v];
    size_t idx = (size_t)v * DV + (lane < 12 ? lane : 0);
    float4 gv = __ldg(&gin[idx]);      // self loop term
    float4 xx = __ldg(&x[idx]);

    float4 a0 = make_float4(0.f, 0.f, 0.f, 0.f);
    float4 a1 = a0, a2 = a0;
    float4 b0 = a0, b1 = a0, b2 = a0;

    int b = s;
    for (; b + 16 <= eend; b += 16) {          // 16 edges/iter, unguarded
        int r0 = __ldg(&g_csr_row[b + el]);
        int r1 = __ldg(&g_csr_row[b + 8 + el]);
        const float4* p0 = gin + (size_t)r0 * DV;
        const float4* p1 = gin + (size_t)r1 * DV;
        float4 u0 = __ldg(&p0[q]);
        float4 u1 = __ldg(&p0[q + 4]);
        float4 u2 = __ldg(&p0[q + 8]);
        float4 w0 = __ldg(&p1[q]);
        float4 w1 = __ldg(&p1[q + 4]);
        float4 w2 = __ldg(&p1[q + 8]);
        a0 = f4add(a0, u0);  a1 = f4add(a1, u1);  a2 = f4add(a2, u2);
        b0 = f4add(b0, w0);  b1 = f4add(b1, w1);  b2 = f4add(b2, w2);
    }
    for (; b < eend; b += 8) {                 // guarded 8-edge tail
        int e = b + el;
        if (e < eend) {
            int r = __ldg(&g_csr_row[e]);
            const float4* p = gin + (size_t)r * DV;
            a0 = f4add(a0, __ldg(&p[q]));
            a1 = f4add(a1, __ldg(&p[q + 4]));
            a2 = f4add(a2, __ldg(&p[q + 8]));
        }
    }
    a0 = f4add(a0, b0);  a1 = f4add(a1, b1);  a2 = f4add(a2, b2);

    // reduce across the 8 edge slots (lane bits 2..4)
    #pragma unroll
    for (int off = 4; off <= 16; off <<= 1) {
        a0.x += __shfl_xor_sync(0xffffffffu, a0.x, off);
        a0.y += __shfl_xor_sync(0xffffffffu, a0.y, off);
        a0.z += __shfl_xor_sync(0xffffffffu, a0.z, off);
        a0.w += __shfl_xor_sync(0xffffffffu, a0.w, off);
        a1.x += __shfl_xor_sync(0xffffffffu, a1.x, off);
        a1.y += __shfl_xor_sync(0xffffffffu, a1.y, off);
        a1.z += __shfl_xor_sync(0xffffffffu, a1.z, off);
        a1.w += __shfl_xor_sync(0xffffffffu, a1.w, off);
        a2.x += __shfl_xor_sync(0xffffffffu, a2.x, off);
        a2.y += __shfl_xor_sync(0xffffffffu, a2.y, off);
        a2.z += __shfl_xor_sync(0xffffffffu, a2.z, off);
        a2.w += __shfl_xor_sync(0xffffffffu, a2.w, off);
    }

    // lanes 0..11 each own output chunk `lane`
    if (lane < 12) {
        int sel = lane >> 2;
        float4 val = (sel == 0) ? a0 : ((sel == 1) ? a1 : a2);

        float4 h;
        h.x = (1.0f - ALPHA) * (di * (val.x + gv.x)) + ALPHA * xx.x;
        h.y = (1.0f - ALPHA) * (di * (val.y + gv.y)) + ALPHA * xx.y;
        h.z = (1.0f - ALPHA) * (di * (val.z + gv.z)) + ALPHA * xx.z;
        h.w = (1.0f - ALPHA) * (di * (val.w + gv.w)) + ALPHA * xx.w;

        if (!WRITE_H) {                      // store g = dinv * h for next step
            h.x *= di; h.y *= di; h.z *= di; h.w *= di;
        }
        gout[(size_t)v * DV + lane] = h;
    }
}

// ---------------- launch ----------------
extern "C" void kernel_launch(void* const* d_in, const int* in_sizes, int n_in,
                              void* d_out, int out_size) {
    const float4* x  = (const float4*)d_in[0];
    const int*    ei = (const int*)d_in[1];
    const int* row = ei;          // edge_index[0]
    const int* col = ei + EE;     // edge_index[1]
    float4* out = (float4*)d_out;

    float4 *pA, *pB;
    cudaGetSymbolAddress((void**)&pA, g_bufA);
    cudaGetSymbolAddress((void**)&pB, g_bufB);

    k_hist<<<(EE + 255) / 256, 256>>>(col);                       // launch 1
    k_alloc<<<(NN + 255) / 256, 256>>>();                         // launch 2
    k_scatter_fused<<<(EE + 255) / 256, 256>>>(row, col, x, pA);  // launch 3

    const int PBLK = 256;                       // 8 warps = 8 nodes per block
    const int PGRID = (NN + 7) / 8;             // 12500
    k_propagate<false><<<PGRID, PBLK>>>(pA, x, pB);   // launch 4 <- profiled
    k_propagate<false><<<PGRID, PBLK>>>(pB, x, pA);
    k_propagate<false><<<PGRID, PBLK>>>(pA, x, pB);
    k_propagate<false><<<PGRID, PBLK>>>(pB, x, pA);
    k_propagate<true ><<<PGRID, PBLK>>>(pA, x, out);  // step 5 -> h
}

// round 8
// speedup vs baseline: 1.1194x; 1.1194x over previous
#include <cuda_runtime.h>

// APPNP: h_{k+1} = (1-a) * Dinv(A+I)Dinv * h_k + a * x,  K=5, a=0.8
// g = dinv .* h (fp32). m[v] = dinv[v]*(g[v] + sum_{e:col=v} g[row_e]).
// 3-kernel preprocessing (hist -> alloc -> fused scatter/scale/rezero).
// Propagate: warp/node, 16 edges/iter, lean registers for occupancy.

#define NN 100000
#define EE 1600000
#define DD 48
#define DV 12           // float4 chunks per fp32 row
#define ALPHA 0.8f

// ---------------- device scratch (static, no allocation) ----------------
__device__ int    g_ecount[NN];     // zero at every kernel_launch entry (invariant)
__device__ int    g_total;          // zero at entry (invariant)
__device__ float  g_dinv[NN];
__device__ int    g_colstart[NN];
__device__ int    g_colend[NN];
__device__ int    g_rank[EE];
__device__ int    g_csr_row[EE];
__device__ float4 g_bufA[NN * DV];
__device__ float4 g_bufB[NN * DV];

static __device__ __forceinline__ float4 f4add(float4 a, float4 b) {
    return make_float4(a.x + b.x, a.y + b.y, a.z + b.z, a.w + b.w);
}

// ---------------- preprocessing ----------------
// histogram; atomic return value = within-node rank of this edge
__global__ void k_hist(const int* __restrict__ col) {
    int e = blockIdx.x * blockDim.x + threadIdx.x;
    if (e < EE) g_rank[e] = atomicAdd(&g_ecount[col[e]], 1);
}

// claim contiguous segment per node; compute dinv
__global__ void k_alloc() {
    int v = blockIdx.x * blockDim.x + threadIdx.x;
    if (v < NN) {
        int c = g_ecount[v];
        int p = atomicAdd(&g_total, c);
        g_colstart[v] = p;
        g_colend[v]   = p + c;
        g_dinv[v]     = rsqrtf((float)(c + 1));   // +1 self loop
    }
}

// scatter (atomic-free) + scale_x + restore zero-invariant for next replay
__global__ void k_scatter_fused(const int* __restrict__ row, const int* __restrict__ col,
                                const float4* __restrict__ x, float4* __restrict__ g0) {
    int t = blockIdx.x * blockDim.x + threadIdx.x;
    if (t < EE) {
        int p = g_colstart[col[t]] + g_rank[t];
        g_csr_row[p] = row[t];
    }
    if (t < NN * DV) {                 // g0 = dinv .* x
        int v = t / DV;
        float s = g_dinv[v];
        float4 a = x[t];
        g0[t] = make_float4(a.x * s, a.y * s, a.z * s, a.w * s);
    }
    if (t < NN) g_ecount[t] = 0;       // ecount dead after k_alloc; re-zero
    if (t == 0) g_total = 0;
}

// ---------------- propagation ----------------
// Warp per node. el = lane>>2 (8 edge slots), q = lane&3.
// Single accumulator trio; 16 edges per main-loop iteration.
template <bool WRITE_H>
__global__ void __launch_bounds__(256, 5) k_propagate(const float4* __restrict__ gin,
                                                      const float4* __restrict__ x,
                                                      float4* __restrict__ gout) {
    int v    = (blockIdx.x * blockDim.x + threadIdx.x) >> 5;
    int lane = threadIdx.x & 31;
    if (v >= NN) return;

    int el = lane >> 2;
    int q  = lane & 3;

    int b    = g_colstart[v];
    int eend = g_colend[v];

    float4 a0 = make_float4(0.f, 0.f, 0.f, 0.f);
    float4 a1 = a0, a2 = a0;

    for (; b + 16 <= eend; b += 16) {          // 16 edges/iter, unguarded
        int r0 = __ldg(&g_csr_row[b + el]);
        int r1 = __ldg(&g_csr_row[b + 8 + el]);
        const float4* p0 = gin + (size_t)r0 * DV;
        const float4* p1 = gin + (size_t)r1 * DV;
        a0 = f4add(a0, __ldg(&p0[q]));
        a1 = f4add(a1, __ldg(&p0[q + 4]));
        a2 = f4add(a2, __ldg(&p0[q + 8]));
        a0 = f4add(a0, __ldg(&p1[q]));
        a1 = f4add(a1, __ldg(&p1[q + 4]));
        a2 = f4add(a2, __ldg(&p1[q + 8]));
    }
    for (; b < eend; b += 8) {                 // guarded 8-edge tail
        int e = b + el;
        if (e < eend) {
            int r = __ldg(&g_csr_row[e]);
            const float4* p = gin + (size_t)r * DV;
            a0 = f4add(a0, __ldg(&p[q]));
            a1 = f4add(a1, __ldg(&p[q + 4]));
            a2 = f4add(a2, __ldg(&p[q + 8]));
        }
    }

    // reduce across the 8 edge slots (lane bits 2..4)
    #pragma unroll
    for (int off = 4; off <= 16; off <<= 1) {
        a0.x += __shfl_xor_sync(0xffffffffu, a0.x, off);
        a0.y += __shfl_xor_sync(0xffffffffu, a0.y, off);
        a0.z += __shfl_xor_sync(0xffffffffu, a0.z, off);
        a0.w += __shfl_xor_sync(0xffffffffu, a0.w, off);
        a1.x += __shfl_xor_sync(0xffffffffu, a1.x, off);
        a1.y += __shfl_xor_sync(0xffffffffu, a1.y, off);
        a1.z += __shfl_xor_sync(0xffffffffu, a1.z, off);
        a1.w += __shfl_xor_sync(0xffffffffu, a1.w, off);
        a2.x += __shfl_xor_sync(0xffffffffu, a2.x, off);
        a2.y += __shfl_xor_sync(0xffffffffu, a2.y, off);
        a2.z += __shfl_xor_sync(0xffffffffu, a2.z, off);
        a2.w += __shfl_xor_sync(0xffffffffu, a2.w, off);
    }

    // lanes 0..11 each own output chunk `lane`
    if (lane < 12) {
        int sel = lane >> 2;
        float4 val = (sel == 0) ? a0 : ((sel == 1) ? a1 : a2);

        float  di = g_dinv[v];
        size_t idx = (size_t)v * DV + lane;
        float4 gv = __ldg(&gin[idx]);        // self loop: + g[v]
        float4 xx = __ldg(&x[idx]);

        float4 h;
        h.x = (1.0f - ALPHA) * (di * (val.x + gv.x)) + ALPHA * xx.x;
        h.y = (1.0f - ALPHA) * (di * (val.y + gv.y)) + ALPHA * xx.y;
        h.z = (1.0f - ALPHA) * (di * (val.z + gv.z)) + ALPHA * xx.z;
        h.w = (1.0f - ALPHA) * (di * (val.w + gv.w)) + ALPHA * xx.w;

        if (!WRITE_H) {                      // store g = dinv * h for next step
            h.x *= di; h.y *= di; h.z *= di; h.w *= di;
        }
        gout[idx] = h;
    }
}

// ---------------- launch ----------------
extern "C" void kernel_launch(void* const* d_in, const int* in_sizes, int n_in,
                              void* d_out, int out_size) {
    const float4* x  = (const float4*)d_in[0];
    const int*    ei = (const int*)d_in[1];
    const int* row = ei;          // edge_index[0]
    const int* col = ei + EE;     // edge_index[1]
    float4* out = (float4*)d_out;

    float4 *pA, *pB;
    cudaGetSymbolAddress((void**)&pA, g_bufA);
    cudaGetSymbolAddress((void**)&pB, g_bufB);

    k_hist<<<(EE + 255) / 256, 256>>>(col);                       // launch 1
    k_alloc<<<(NN + 255) / 256, 256>>>();                         // launch 2
    k_scatter_fused<<<(EE + 255) / 256, 256>>>(row, col, x, pA);  // launch 3

    const int PBLK = 256;                       // 8 warps = 8 nodes per block
    const int PGRID = (NN + 7) / 8;             // 12500
    k_propagate<false><<<PGRID, PBLK>>>(pA, x, pB);   // launch 4 <- profiled
    k_propagate<false><<<PGRID, PBLK>>>(pB, x, pA);
    k_propagate<false><<<PGRID, PBLK>>>(pA, x, pB);
    k_propagate<false><<<PGRID, PBLK>>>(pB, x, pA);
    k_propagate<true ><<<PGRID, PBLK>>>(pA, x, out);  // step 5 -> h
}

// round 9
// speedup vs baseline: 1.3759x; 1.2291x over previous
#include <cuda_runtime.h>

// APPNP: h_{k+1} = (1-a) * Dinv(A+I)Dinv * h_k + a * x,  K=5, a=0.8
// g = dinv .* h (fp32, float2 rows of 24). m[v] = dinv[v]*(g[v] + sum g[row_e]).
// DIM-PARALLEL propagate: lane<24 owns one float2 of the row -> no reduction,
// 4 regs of accumulator, 2 L1 wavefronts per edge. CSR segments padded to
// multiples of 4 pointing at a permanent zero row (row NN) -> uniform int4
// index loads, no tail.

#define NN 100000
#define EE 1600000
#define F2 24               // float2 per row (48 floats)
#define CSR_CAP (EE + 3 * NN + 4)
#define ALPHA 0.8f

// ---------------- device scratch (static, no allocation) ----------------
__device__ int    g_ecount[NN];     // zero at every kernel_launch entry (invariant)
__device__ int    g_total;          // zero at entry (invariant)
__device__ float  g_dinv[NN];
__device__ int    g_colstart[NN];
__device__ int    g_colend[NN];     // padded end (multiple-of-4 segment)
__device__ int    g_rank[EE];
__device__ int4   g_csr4[CSR_CAP / 4 + 1];          // 16B-aligned row indices
__device__ float2 g_bufA[(NN + 1) * F2];            // row NN = permanent zeros
__device__ float2 g_bufB[(NN + 1) * F2];            // (never written)

// ---------------- preprocessing ----------------
// histogram; atomic return value = within-node rank of this edge
__global__ void k_hist(const int* __restrict__ col) {
    int e = blockIdx.x * blockDim.x + threadIdx.x;
    if (e < EE) g_rank[e] = atomicAdd(&g_ecount[col[e]], 1);
}

// claim 4-aligned contiguous segment per node; pad with zero-row index NN
__global__ void k_alloc() {
    int v = blockIdx.x * blockDim.x + threadIdx.x;
    if (v < NN) {
        int c  = g_ecount[v];
        int cp = (c + 3) & ~3;
        int p  = atomicAdd(&g_total, cp);        // g_total starts 0 -> p 4-aligned
        g_colstart[v] = p;
        g_colend[v]   = p + cp;
        int* csr = (int*)g_csr4;
        for (int j = c; j < cp; j++) csr[p + j] = NN;   // zero-row padding
        g_dinv[v] = rsqrtf((float)(c + 1));      // +1 self loop
    }
}

// scatter (atomic-free) + g0 = dinv.*x + restore zero-invariant for next replay
__global__ void k_scatter_fused(const int* __restrict__ row, const int* __restrict__ col,
                                const float2* __restrict__ x2, float2* __restrict__ g0) {
    int t = blockIdx.x * blockDim.x + threadIdx.x;
    if (t < EE) {
        int p = g_colstart[col[t]] + g_rank[t];
        ((int*)g_csr4)[p] = row[t];
    }
    if (t < NN * F2) {                 // g0 = dinv .* x
        int v = t / F2;
        float s = g_dinv[v];
        float2 a = x2[t];
        g0[t] = make_float2(a.x * s, a.y * s);
    }
    if (t < NN) g_ecount[t] = 0;       // ecount dead after k_alloc; re-zero
    if (t == 0) g_total = 0;
}

// ---------------- propagation ----------------
// Warp per node; lane<24 owns float2 chunk `lane` of the 48-dim row.
template <bool WRITE_H>
__global__ void __launch_bounds__(256, 6) k_propagate(const float2* __restrict__ gin,
                                                      const float2* __restrict__ x2,
                                                      float2* __restrict__ gout) {
    int v    = (blockIdx.x * blockDim.x + threadIdx.x) >> 5;
    int lane = threadIdx.x & 31;
    if (v >= NN) return;

    int b   = g_colstart[v];
    int end = g_colend[v];                 // multiple-of-4 segment, no tail
    bool act = (lane < F2);

    float2 acc0 = make_float2(0.f, 0.f);
    float2 acc1 = make_float2(0.f, 0.f);

    #pragma unroll 2
    for (; b < end; b += 4) {
        int4 r = __ldg(&g_csr4[b >> 2]);   // uniform: 4 edge indices, 1 wavefront
        if (act) {
            float2 u0 = __ldg(&gin[r.x * F2 + lane]);
            float2 u1 = __ldg(&gin[r.y * F2 + lane]);
            float2 u2 = __ldg(&gin[r.z * F2 + lane]);
            float2 u3 = __ldg(&gin[r.w * F2 + lane]);
            acc0.x += u0.x; acc0.y += u0.y;
            acc1.x += u1.x; acc1.y += u1.y;
            acc0.x += u2.x; acc0.y += u2.y;
            acc1.x += u3.x; acc1.y += u3.y;
        }
    }

    if (act) {
        float di  = g_dinv[v];
        int   idx = v * F2 + lane;
        float2 gv = __ldg(&gin[idx]);      // self loop
        float2 xx = __ldg(&x2[idx]);

        float2 h;
        h.x = (1.0f - ALPHA) * (di * (acc0.x + acc1.x + gv.x)) + ALPHA * xx.x;
        h.y = (1.0f - ALPHA) * (di * (acc0.y + acc1.y + gv.y)) + ALPHA * xx.y;

        if (!WRITE_H) {                    // store g = dinv * h for next step
            h.x *= di; h.y *= di;
        }
        gout[idx] = h;
    }
}

// ---------------- launch ----------------
extern "C" void kernel_launch(void* const* d_in, const int* in_sizes, int n_in,
                              void* d_out, int out_size) {
    const float2* x2 = (const float2*)d_in[0];
    const int*    ei = (const int*)d_in[1];
    const int* row = ei;          // edge_index[0]
    const int* col = ei + EE;     // edge_index[1]
    float2* out = (float2*)d_out;

    float2 *pA, *pB;
    cudaGetSymbolAddress((void**)&pA, g_bufA);
    cudaGetSymbolAddress((void**)&pB, g_bufB);

    k_hist<<<(EE + 255) / 256, 256>>>(col);                        // launch 1
    k_alloc<<<(NN + 255) / 256, 256>>>();                          // launch 2
    const int FT = NN * F2;                                        // 2.4M threads
    k_scatter_fused<<<(FT + 255) / 256, 256>>>(row, col, x2, pA);  // launch 3

    const int PBLK = 256;                       // 8 warps = 8 nodes per block
    const int PGRID = (NN + 7) / 8;             // 12500
    k_propagate<false><<<PGRID, PBLK>>>(pA, x2, pB);   // launch 4 <- profiled
    k_propagate<false><<<PGRID, PBLK>>>(pB, x2, pA);
    k_propagate<false><<<PGRID, PBLK>>>(pA, x2, pB);
    k_propagate<false><<<PGRID, PBLK>>>(pB, x2, pA);
    k_propagate<true ><<<PGRID, PBLK>>>(pA, x2, out);  // step 5 -> h
}